// round 6
// baseline (speedup 1.0000x reference)
#include <cuda_runtime.h>
#include <cuda_fp16.h>
#include <cstdint>

#define NUM_USERS 100000
#define NUM_ITEMS 200000
#define NN (NUM_USERS + NUM_ITEMS)   // 300000
#define EE 2000000
#define DD 64
#define TOT (NN * DD)                // 19,200,000
#define TOT8 (TOT / 8)
#define U8  (NUM_USERS * DD / 8)

#define SCAN_ITEMS 1024
#define SCAN_BLOCKS ((NN + SCAN_ITEMS - 1) / SCAN_ITEMS)   // 293

// ---- allocation-free scratch -----------------------------------------------
__device__ __half g_h0[TOT];       // ego in fp16
__device__ __half g_bufA[TOT];     // h1
__device__ __half g_bufB[TOT];     // h2
__device__ int    g_cnt[NN];       // histogram -> scatter cursor
__device__ int    g_rowptr[NN + 1];
__device__ int    g_bsums[512];
__device__ int2   g_edges[EE];     // (col, val bits) sorted by row

__device__ __forceinline__ uint32_t h2u(__half2 h) { return *reinterpret_cast<uint32_t*>(&h); }
__device__ __forceinline__ __half2  u2h(uint32_t u) { return *reinterpret_cast<__half2*>(&u); }

// ---------------------------------------------------------------------------
// conv: g_h0 = fp16(concat(ue, ie)); also zeroes g_cnt (runs before hist).
// ---------------------------------------------------------------------------
__global__ void __launch_bounds__(256) conv_kernel(const float4* __restrict__ ue,
                                                   const float4* __restrict__ ie) {
    int i = blockIdx.x * blockDim.x + threadIdx.x;
    if (i < NN) g_cnt[i] = 0;
    if (i >= TOT8) return;
    float4 f0, f1;
    if (i < U8) {
        f0 = __ldg(&ue[2 * i]);        f1 = __ldg(&ue[2 * i + 1]);
    } else {
        f0 = __ldg(&ie[2 * (i - U8)]); f1 = __ldg(&ie[2 * (i - U8) + 1]);
    }
    uint4 h;
    h.x = h2u(__float22half2_rn(make_float2(f0.x, f0.y)));
    h.y = h2u(__float22half2_rn(make_float2(f0.z, f0.w)));
    h.z = h2u(__float22half2_rn(make_float2(f1.x, f1.y)));
    h.w = h2u(__float22half2_rn(make_float2(f1.z, f1.w)));
    reinterpret_cast<uint4*>(g_h0)[i] = h;
}

// ---------------------------------------------------------------------------
// histogram
// ---------------------------------------------------------------------------
__global__ void __launch_bounds__(256) hist_kernel(const int* __restrict__ rows) {
    int e = blockIdx.x * blockDim.x + threadIdx.x;
    if (e >= EE) return;
    atomicAdd(&g_cnt[__ldcs(&rows[e])], 1);
}

// ---------------------------------------------------------------------------
// scan stage 1: per-block inclusive scan of g_cnt
// ---------------------------------------------------------------------------
__global__ void __launch_bounds__(256) scan_block_kernel() {
    __shared__ int warp_sums[8];
    int tid = threadIdx.x;
    int idx = blockIdx.x * SCAN_ITEMS + tid * 4;
    int v0 = 0, v1 = 0, v2 = 0, v3 = 0;
    if (idx + 3 < NN) {
        int4 t = *reinterpret_cast<const int4*>(&g_cnt[idx]);
        v0 = t.x; v1 = t.y; v2 = t.z; v3 = t.w;
    } else {
        if (idx     < NN) v0 = g_cnt[idx];
        if (idx + 1 < NN) v1 = g_cnt[idx + 1];
        if (idx + 2 < NN) v2 = g_cnt[idx + 2];
        if (idx + 3 < NN) v3 = g_cnt[idx + 3];
    }
    int s1 = v0 + v1, s2 = s1 + v2, s3 = s2 + v3;
    int lane = tid & 31, wid = tid >> 5;
    int x = s3;
    #pragma unroll
    for (int d = 1; d < 32; d <<= 1) {
        int y = __shfl_up_sync(0xffffffffu, x, d);
        if (lane >= d) x += y;
    }
    if (lane == 31) warp_sums[wid] = x;
    __syncthreads();
    if (wid == 0) {
        int w = (lane < 8) ? warp_sums[lane] : 0;
        #pragma unroll
        for (int d = 1; d < 8; d <<= 1) {
            int y = __shfl_up_sync(0xffffffffu, w, d);
            if (lane >= d) w += y;
        }
        if (lane < 8) warp_sums[lane] = w;
    }
    __syncthreads();
    int warp_off = (wid > 0) ? warp_sums[wid - 1] : 0;
    int te = warp_off + x - s3;
    if (idx     < NN) g_rowptr[idx + 1] = te + v0;
    if (idx + 1 < NN) g_rowptr[idx + 2] = te + s1;
    if (idx + 2 < NN) g_rowptr[idx + 3] = te + s2;
    if (idx + 3 < NN) g_rowptr[idx + 4] = te + s3;
    if (tid == 0) {
        g_bsums[blockIdx.x] = warp_sums[7];
        if (blockIdx.x == 0) g_rowptr[0] = 0;
    }
}

// ---------------------------------------------------------------------------
// scan stage 2: exclusive scan of block sums
// ---------------------------------------------------------------------------
__global__ void __launch_bounds__(512) scan_sums_kernel() {
    __shared__ int ws[16];
    int tid = threadIdx.x;
    int v = (tid < SCAN_BLOCKS) ? g_bsums[tid] : 0;
    int lane = tid & 31, wid = tid >> 5;
    int x = v;
    #pragma unroll
    for (int d = 1; d < 32; d <<= 1) {
        int y = __shfl_up_sync(0xffffffffu, x, d);
        if (lane >= d) x += y;
    }
    if (lane == 31) ws[wid] = x;
    __syncthreads();
    if (wid == 0) {
        int w = (lane < 16) ? ws[lane] : 0;
        #pragma unroll
        for (int d = 1; d < 16; d <<= 1) {
            int y = __shfl_up_sync(0xffffffffu, w, d);
            if (lane >= d) w += y;
        }
        if (lane < 16) ws[lane] = w;
    }
    __syncthreads();
    int off = (wid > 0) ? ws[wid - 1] : 0;
    if (tid < SCAN_BLOCKS) g_bsums[tid] = off + x - v;
}

// ---------------------------------------------------------------------------
// scan stage 3: add block offsets; set scatter cursors
// ---------------------------------------------------------------------------
__global__ void __launch_bounds__(256) scan_add_kernel() {
    int r = blockIdx.x * blockDim.x + threadIdx.x;
    if (r >= NN) return;
    int ex = g_bsums[r / SCAN_ITEMS];
    int inc = g_rowptr[r + 1] + ex;
    g_rowptr[r + 1] = inc;
    g_cnt[r] = inc - g_cnt[r];
}

// ---------------------------------------------------------------------------
// scatter edges into row buckets
// ---------------------------------------------------------------------------
__global__ void __launch_bounds__(256) scatter_kernel(const int* __restrict__ rows,
                                                      const int* __restrict__ cols,
                                                      const float* __restrict__ vals) {
    int e = blockIdx.x * blockDim.x + threadIdx.x;
    if (e >= EE) return;
    int r = __ldcs(&rows[e]);
    int c = __ldcs(&cols[e]);
    float v = __ldcs(&vals[e]);
    int pos = atomicAdd(&g_cnt[r], 1);
    g_edges[pos] = make_int2(c, __float_as_int(v));
}

// ---------------------------------------------------------------------------
// CSR row accumulation core: 8 threads/row, fp32 accum, 1-deep prefetch.
// ---------------------------------------------------------------------------
__device__ __forceinline__ void csr_accum(int row, int ch,
                                          const __half* __restrict__ src,
                                          float2& a0, float2& a1,
                                          float2& a2, float2& a3) {
    int e   = __ldg(&g_rowptr[row]);
    int end = __ldg(&g_rowptr[row + 1]);
    a0 = make_float2(0.f, 0.f); a1 = a0; a2 = a0; a3 = a0;
    if (e >= end) return;
    int2 ev = __ldg(&g_edges[e]);
    uint4 x = __ldg(reinterpret_cast<const uint4*>(src + (size_t)ev.x * DD + ch));
    while (true) {
        int2 ev_c = ev;
        uint4 x_c = x;
        ++e;
        if (e < end) {
            ev = __ldg(&g_edges[e]);
            x  = __ldg(reinterpret_cast<const uint4*>(src + (size_t)ev.x * DD + ch));
        }
        float v = __int_as_float(ev_c.y);
        float2 f0 = __half22float2(u2h(x_c.x));
        float2 f1 = __half22float2(u2h(x_c.y));
        float2 f2 = __half22float2(u2h(x_c.z));
        float2 f3 = __half22float2(u2h(x_c.w));
        a0.x += v * f0.x; a0.y += v * f0.y;
        a1.x += v * f1.x; a1.y += v * f1.y;
        a2.x += v * f2.x; a2.y += v * f2.y;
        a3.x += v * f3.x; a3.y += v * f3.y;
        if (e >= end) break;
    }
}

// layers 1 & 2: store fp16
__global__ void __launch_bounds__(256) csr_spmm_kernel(const __half* __restrict__ src,
                                                       __half* __restrict__ dst) {
    int t = blockIdx.x * blockDim.x + threadIdx.x;
    int row = t >> 3;
    if (row >= NN) return;
    int ch = (t & 7) << 3;
    float2 a0, a1, a2, a3;
    csr_accum(row, ch, src, a0, a1, a2, a3);
    uint4 o;
    o.x = h2u(__float22half2_rn(a0));
    o.y = h2u(__float22half2_rn(a1));
    o.z = h2u(__float22half2_rn(a2));
    o.w = h2u(__float22half2_rn(a3));
    *reinterpret_cast<uint4*>(dst + (size_t)row * DD + ch) = o;
}

// layer 3 fused with final: out = (ego + h1 + h2 + h3)*0.25, fp32
__global__ void __launch_bounds__(256) csr_spmm_final_kernel(
    const float4* __restrict__ ue, const float4* __restrict__ ie,
    float4* __restrict__ out) {
    int t = blockIdx.x * blockDim.x + threadIdx.x;
    int row = t >> 3;
    if (row >= NN) return;
    int ch = (t & 7) << 3;
    float2 a0, a1, a2, a3;
    csr_accum(row, ch, g_bufB, a0, a1, a2, a3);   // h3 accum from h2

    size_t base = (size_t)row * DD + ch;
    // ego fp32: two float4s
    float4 e0, e1;
    if (row < NUM_USERS) {
        e0 = __ldg(&ue[base / 4]);       e1 = __ldg(&ue[base / 4 + 1]);
    } else {
        size_t ib = base - (size_t)NUM_USERS * DD;
        e0 = __ldg(&ie[ib / 4]);         e1 = __ldg(&ie[ib / 4 + 1]);
    }
    // h1, h2 chunks (own row, coalesced)
    uint4 uh1 = __ldg(reinterpret_cast<const uint4*>(g_bufA + base));
    uint4 uh2 = __ldg(reinterpret_cast<const uint4*>(g_bufB + base));
    float2 h10 = __half22float2(u2h(uh1.x)), h11 = __half22float2(u2h(uh1.y));
    float2 h12 = __half22float2(u2h(uh1.z)), h13 = __half22float2(u2h(uh1.w));
    float2 h20 = __half22float2(u2h(uh2.x)), h21 = __half22float2(u2h(uh2.y));
    float2 h22 = __half22float2(u2h(uh2.z)), h23 = __half22float2(u2h(uh2.w));

    float4 o0, o1;
    o0.x = (e0.x + h10.x + h20.x + a0.x) * 0.25f;
    o0.y = (e0.y + h10.y + h20.y + a0.y) * 0.25f;
    o0.z = (e0.z + h11.x + h21.x + a1.x) * 0.25f;
    o0.w = (e0.w + h11.y + h21.y + a1.y) * 0.25f;
    o1.x = (e1.x + h12.x + h22.x + a2.x) * 0.25f;
    o1.y = (e1.y + h12.y + h22.y + a2.y) * 0.25f;
    o1.z = (e1.z + h13.x + h23.x + a3.x) * 0.25f;
    o1.w = (e1.w + h13.y + h23.y + a3.y) * 0.25f;
    out[base / 4]     = o0;
    out[base / 4 + 1] = o1;
}

extern "C" void kernel_launch(void* const* d_in, const int* in_sizes, int n_in,
                              void* d_out, int out_size) {
    const float* user_emb = (const float*)d_in[0];
    const float* item_emb = (const float*)d_in[1];
    const int*   adj_rows = (const int*)d_in[2];
    const int*   adj_cols = (const int*)d_in[3];
    const float* adj_vals = (const float*)d_in[4];
    float* out = (float*)d_out;

    __half *h0, *bufA, *bufB;
    cudaGetSymbolAddress((void**)&h0,   g_h0);
    cudaGetSymbolAddress((void**)&bufA, g_bufA);
    cudaGetSymbolAddress((void**)&bufB, g_bufB);

    const int T = 256;
    const int CONV_BLOCKS = (TOT8 + T - 1) / T;
    const int EDGE_BLOCKS = (EE + T - 1) / T;
    const int ROW_BLOCKS  = (NN + T - 1) / T;
    const int SPMM_BLOCKS = (NN * 8 + T - 1) / T;

    // conv also zeroes g_cnt (ordering: conv -> hist on same stream)
    conv_kernel<<<CONV_BLOCKS, T>>>((const float4*)user_emb, (const float4*)item_emb);
    hist_kernel<<<EDGE_BLOCKS, T>>>(adj_rows);
    scan_block_kernel<<<SCAN_BLOCKS, T>>>();
    scan_sums_kernel<<<1, 512>>>();
    scan_add_kernel<<<ROW_BLOCKS, T>>>();
    scatter_kernel<<<EDGE_BLOCKS, T>>>(adj_rows, adj_cols, adj_vals);

    // h1 = A @ h0 ; h2 = A @ h1 ; out = (ego + h1 + h2 + A @ h2)/4
    csr_spmm_kernel<<<SPMM_BLOCKS, T>>>(h0,   bufA);
    csr_spmm_kernel<<<SPMM_BLOCKS, T>>>(bufA, bufB);
    csr_spmm_final_kernel<<<SPMM_BLOCKS, T>>>((const float4*)user_emb,
                                              (const float4*)item_emb, (float4*)out);
}

// round 7
// speedup vs baseline: 1.2816x; 1.2816x over previous
#include <cuda_runtime.h>
#include <cuda_fp16.h>
#include <cstdint>

#define NUM_USERS 100000
#define NUM_ITEMS 200000
#define NN (NUM_USERS + NUM_ITEMS)   // 300000
#define EE 2000000
#define DD 64
#define TOT (NN * DD)                // 19,200,000
#define TOT8 (TOT / 8)
#define U8  (NUM_USERS * DD / 8)

#define SCAN_ITEMS 1024
#define SCAN_BLOCKS ((NN + SCAN_ITEMS - 1) / SCAN_ITEMS)   // 293

// ---- allocation-free scratch -----------------------------------------------
__device__ __half g_h0[TOT];       // ego in fp16
__device__ __half g_bufA[TOT];     // h1
__device__ __half g_bufB[TOT];     // h2
__device__ int    g_cnt[NN];       // histogram -> scatter cursor
__device__ int    g_rowptr[NN + 1];
__device__ int    g_bsums[512];
__device__ int2   g_edges[EE];     // (col, val bits) sorted by row

__device__ __forceinline__ uint32_t h2u(__half2 h) { return *reinterpret_cast<uint32_t*>(&h); }
__device__ __forceinline__ __half2  u2h(uint32_t u) { return *reinterpret_cast<__half2*>(&u); }

// ---------------------------------------------------------------------------
// conv: g_h0 = fp16(concat(ue, ie)); also zeroes g_cnt (runs before hist).
// ---------------------------------------------------------------------------
__global__ void __launch_bounds__(256) conv_kernel(const float4* __restrict__ ue,
                                                   const float4* __restrict__ ie) {
    int i = blockIdx.x * blockDim.x + threadIdx.x;
    if (i < NN) g_cnt[i] = 0;
    if (i >= TOT8) return;
    float4 f0, f1;
    if (i < U8) {
        f0 = __ldg(&ue[2 * i]);        f1 = __ldg(&ue[2 * i + 1]);
    } else {
        f0 = __ldg(&ie[2 * (i - U8)]); f1 = __ldg(&ie[2 * (i - U8) + 1]);
    }
    uint4 h;
    h.x = h2u(__float22half2_rn(make_float2(f0.x, f0.y)));
    h.y = h2u(__float22half2_rn(make_float2(f0.z, f0.w)));
    h.z = h2u(__float22half2_rn(make_float2(f1.x, f1.y)));
    h.w = h2u(__float22half2_rn(make_float2(f1.z, f1.w)));
    reinterpret_cast<uint4*>(g_h0)[i] = h;
}

// ---------------------------------------------------------------------------
// histogram
// ---------------------------------------------------------------------------
__global__ void __launch_bounds__(256) hist_kernel(const int* __restrict__ rows) {
    int e = blockIdx.x * blockDim.x + threadIdx.x;
    if (e >= EE) return;
    atomicAdd(&g_cnt[__ldcs(&rows[e])], 1);
}

// ---------------------------------------------------------------------------
// scan stage 1: per-block inclusive scan of g_cnt
// ---------------------------------------------------------------------------
__global__ void __launch_bounds__(256) scan_block_kernel() {
    __shared__ int warp_sums[8];
    int tid = threadIdx.x;
    int idx = blockIdx.x * SCAN_ITEMS + tid * 4;
    int v0 = 0, v1 = 0, v2 = 0, v3 = 0;
    if (idx + 3 < NN) {
        int4 t = *reinterpret_cast<const int4*>(&g_cnt[idx]);
        v0 = t.x; v1 = t.y; v2 = t.z; v3 = t.w;
    } else {
        if (idx     < NN) v0 = g_cnt[idx];
        if (idx + 1 < NN) v1 = g_cnt[idx + 1];
        if (idx + 2 < NN) v2 = g_cnt[idx + 2];
        if (idx + 3 < NN) v3 = g_cnt[idx + 3];
    }
    int s1 = v0 + v1, s2 = s1 + v2, s3 = s2 + v3;
    int lane = tid & 31, wid = tid >> 5;
    int x = s3;
    #pragma unroll
    for (int d = 1; d < 32; d <<= 1) {
        int y = __shfl_up_sync(0xffffffffu, x, d);
        if (lane >= d) x += y;
    }
    if (lane == 31) warp_sums[wid] = x;
    __syncthreads();
    if (wid == 0) {
        int w = (lane < 8) ? warp_sums[lane] : 0;
        #pragma unroll
        for (int d = 1; d < 8; d <<= 1) {
            int y = __shfl_up_sync(0xffffffffu, w, d);
            if (lane >= d) w += y;
        }
        if (lane < 8) warp_sums[lane] = w;
    }
    __syncthreads();
    int warp_off = (wid > 0) ? warp_sums[wid - 1] : 0;
    int te = warp_off + x - s3;
    if (idx     < NN) g_rowptr[idx + 1] = te + v0;
    if (idx + 1 < NN) g_rowptr[idx + 2] = te + s1;
    if (idx + 2 < NN) g_rowptr[idx + 3] = te + s2;
    if (idx + 3 < NN) g_rowptr[idx + 4] = te + s3;
    if (tid == 0) {
        g_bsums[blockIdx.x] = warp_sums[7];
        if (blockIdx.x == 0) g_rowptr[0] = 0;
    }
}

// ---------------------------------------------------------------------------
// scan stage 2: exclusive scan of block sums
// ---------------------------------------------------------------------------
__global__ void __launch_bounds__(512) scan_sums_kernel() {
    __shared__ int ws[16];
    int tid = threadIdx.x;
    int v = (tid < SCAN_BLOCKS) ? g_bsums[tid] : 0;
    int lane = tid & 31, wid = tid >> 5;
    int x = v;
    #pragma unroll
    for (int d = 1; d < 32; d <<= 1) {
        int y = __shfl_up_sync(0xffffffffu, x, d);
        if (lane >= d) x += y;
    }
    if (lane == 31) ws[wid] = x;
    __syncthreads();
    if (wid == 0) {
        int w = (lane < 16) ? ws[lane] : 0;
        #pragma unroll
        for (int d = 1; d < 16; d <<= 1) {
            int y = __shfl_up_sync(0xffffffffu, w, d);
            if (lane >= d) w += y;
        }
        if (lane < 16) ws[lane] = w;
    }
    __syncthreads();
    int off = (wid > 0) ? ws[wid - 1] : 0;
    if (tid < SCAN_BLOCKS) g_bsums[tid] = off + x - v;
}

// ---------------------------------------------------------------------------
// scan stage 3: add block offsets; set scatter cursors
// ---------------------------------------------------------------------------
__global__ void __launch_bounds__(256) scan_add_kernel() {
    int r = blockIdx.x * blockDim.x + threadIdx.x;
    if (r >= NN) return;
    int ex = g_bsums[r / SCAN_ITEMS];
    int inc = g_rowptr[r + 1] + ex;
    g_rowptr[r + 1] = inc;
    g_cnt[r] = inc - g_cnt[r];
}

// ---------------------------------------------------------------------------
// scatter edges into row buckets
// ---------------------------------------------------------------------------
__global__ void __launch_bounds__(256) scatter_kernel(const int* __restrict__ rows,
                                                      const int* __restrict__ cols,
                                                      const float* __restrict__ vals) {
    int e = blockIdx.x * blockDim.x + threadIdx.x;
    if (e >= EE) return;
    int r = __ldcs(&rows[e]);
    int c = __ldcs(&cols[e]);
    float v = __ldcs(&vals[e]);
    int pos = atomicAdd(&g_cnt[r], 1);
    g_edges[pos] = make_int2(c, __float_as_int(v));
}

// ---------------------------------------------------------------------------
// CSR row accumulation core (R5 version: simple loop, unroll 2, ptxas batches
// the independent loads). 8 threads/row, fp32 accumulation.
// ---------------------------------------------------------------------------
__device__ __forceinline__ void csr_accum(int row, int ch,
                                          const __half* __restrict__ src,
                                          float2& a0, float2& a1,
                                          float2& a2, float2& a3) {
    int e   = __ldg(&g_rowptr[row]);
    int end = __ldg(&g_rowptr[row + 1]);
    a0 = make_float2(0.f, 0.f); a1 = a0; a2 = a0; a3 = a0;
    #pragma unroll 2
    for (; e < end; e++) {
        int2 ev = __ldg(&g_edges[e]);
        float v = __int_as_float(ev.y);
        uint4 x = __ldg(reinterpret_cast<const uint4*>(src + (size_t)ev.x * DD + ch));
        float2 f0 = __half22float2(u2h(x.x));
        float2 f1 = __half22float2(u2h(x.y));
        float2 f2 = __half22float2(u2h(x.z));
        float2 f3 = __half22float2(u2h(x.w));
        a0.x += v * f0.x; a0.y += v * f0.y;
        a1.x += v * f1.x; a1.y += v * f1.y;
        a2.x += v * f2.x; a2.y += v * f2.y;
        a3.x += v * f3.x; a3.y += v * f3.y;
    }
}

// layers 1 & 2: store fp16
__global__ void __launch_bounds__(256) csr_spmm_kernel(const __half* __restrict__ src,
                                                       __half* __restrict__ dst) {
    int t = blockIdx.x * blockDim.x + threadIdx.x;
    int row = t >> 3;
    if (row >= NN) return;
    int ch = (t & 7) << 3;
    float2 a0, a1, a2, a3;
    csr_accum(row, ch, src, a0, a1, a2, a3);
    uint4 o;
    o.x = h2u(__float22half2_rn(a0));
    o.y = h2u(__float22half2_rn(a1));
    o.z = h2u(__float22half2_rn(a2));
    o.w = h2u(__float22half2_rn(a3));
    *reinterpret_cast<uint4*>(dst + (size_t)row * DD + ch) = o;
}

// layer 3 fused with final: out = (ego + h1 + h2 + h3)*0.25, fp32
__global__ void __launch_bounds__(256) csr_spmm_final_kernel(
    const float4* __restrict__ ue, const float4* __restrict__ ie,
    float4* __restrict__ out) {
    int t = blockIdx.x * blockDim.x + threadIdx.x;
    int row = t >> 3;
    if (row >= NN) return;
    int ch = (t & 7) << 3;
    float2 a0, a1, a2, a3;
    csr_accum(row, ch, g_bufB, a0, a1, a2, a3);   // h3 accum from h2

    size_t base = (size_t)row * DD + ch;
    float4 e0, e1;
    if (row < NUM_USERS) {
        e0 = __ldg(&ue[base / 4]);       e1 = __ldg(&ue[base / 4 + 1]);
    } else {
        size_t ib = base - (size_t)NUM_USERS * DD;
        e0 = __ldg(&ie[ib / 4]);         e1 = __ldg(&ie[ib / 4 + 1]);
    }
    uint4 uh1 = __ldg(reinterpret_cast<const uint4*>(g_bufA + base));
    uint4 uh2 = __ldg(reinterpret_cast<const uint4*>(g_bufB + base));
    float2 h10 = __half22float2(u2h(uh1.x)), h11 = __half22float2(u2h(uh1.y));
    float2 h12 = __half22float2(u2h(uh1.z)), h13 = __half22float2(u2h(uh1.w));
    float2 h20 = __half22float2(u2h(uh2.x)), h21 = __half22float2(u2h(uh2.y));
    float2 h22 = __half22float2(u2h(uh2.z)), h23 = __half22float2(u2h(uh2.w));

    float4 o0, o1;
    o0.x = (e0.x + h10.x + h20.x + a0.x) * 0.25f;
    o0.y = (e0.y + h10.y + h20.y + a0.y) * 0.25f;
    o0.z = (e0.z + h11.x + h21.x + a1.x) * 0.25f;
    o0.w = (e0.w + h11.y + h21.y + a1.y) * 0.25f;
    o1.x = (e1.x + h12.x + h22.x + a2.x) * 0.25f;
    o1.y = (e1.y + h12.y + h22.y + a2.y) * 0.25f;
    o1.z = (e1.z + h13.x + h23.x + a3.x) * 0.25f;
    o1.w = (e1.w + h13.y + h23.y + a3.y) * 0.25f;
    out[base / 4]     = o0;
    out[base / 4 + 1] = o1;
}

extern "C" void kernel_launch(void* const* d_in, const int* in_sizes, int n_in,
                              void* d_out, int out_size) {
    const float* user_emb = (const float*)d_in[0];
    const float* item_emb = (const float*)d_in[1];
    const int*   adj_rows = (const int*)d_in[2];
    const int*   adj_cols = (const int*)d_in[3];
    const float* adj_vals = (const float*)d_in[4];
    float* out = (float*)d_out;

    __half *h0, *bufA, *bufB;
    cudaGetSymbolAddress((void**)&h0,   g_h0);
    cudaGetSymbolAddress((void**)&bufA, g_bufA);
    cudaGetSymbolAddress((void**)&bufB, g_bufB);

    const int T = 256;
    const int CONV_BLOCKS = (TOT8 + T - 1) / T;
    const int EDGE_BLOCKS = (EE + T - 1) / T;
    const int ROW_BLOCKS  = (NN + T - 1) / T;
    const int SPMM_BLOCKS = (NN * 8 + T - 1) / T;

    // conv also zeroes g_cnt (ordering: conv -> hist on same stream)
    conv_kernel<<<CONV_BLOCKS, T>>>((const float4*)user_emb, (const float4*)item_emb);
    hist_kernel<<<EDGE_BLOCKS, T>>>(adj_rows);
    scan_block_kernel<<<SCAN_BLOCKS, T>>>();
    scan_sums_kernel<<<1, 512>>>();
    scan_add_kernel<<<ROW_BLOCKS, T>>>();
    scatter_kernel<<<EDGE_BLOCKS, T>>>(adj_rows, adj_cols, adj_vals);

    // h1 = A @ h0 ; h2 = A @ h1 ; out = (ego + h1 + h2 + A @ h2)/4
    csr_spmm_kernel<<<SPMM_BLOCKS, T>>>(h0,   bufA);
    csr_spmm_kernel<<<SPMM_BLOCKS, T>>>(bufA, bufB);
    csr_spmm_final_kernel<<<SPMM_BLOCKS, T>>>((const float4*)user_emb,
                                              (const float4*)item_emb, (float4*)out);
}

// round 8
// speedup vs baseline: 1.2920x; 1.0081x over previous
#include <cuda_runtime.h>
#include <cuda_fp16.h>
#include <cstdint>

#define NUM_USERS 100000
#define NUM_ITEMS 200000
#define NN (NUM_USERS + NUM_ITEMS)   // 300000
#define EE 2000000
#define DD 64
#define TOT (NN * DD)                // 19,200,000
#define TOT8 (TOT / 8)
#define U8  (NUM_USERS * DD / 8)

#define SCAN_TILE 4096               // 256 threads x 16 items
#define NTILES ((NN + SCAN_TILE - 1) / SCAN_TILE)   // 74 (< 148 SMs: co-resident)

// ---- allocation-free scratch -----------------------------------------------
__device__ __half g_h0[TOT];       // ego in fp16
__device__ __half g_bufA[TOT];     // h1
__device__ __half g_bufB[TOT];     // h2
__device__ int    g_cnt[NN];       // histogram -> scatter cursor (zero-init; re-zeroed each call)
__device__ int    g_rowptr[NN + 1];
__device__ unsigned long long g_tile_state[NTILES];  // lookback: (status<<32)|sum; 0=invalid
__device__ int2   g_edges[EE];     // (col, val bits) sorted by row

__device__ __forceinline__ uint32_t h2u(__half2 h) { return *reinterpret_cast<uint32_t*>(&h); }
__device__ __forceinline__ __half2  u2h(uint32_t u) { return *reinterpret_cast<__half2*>(&u); }

// ---------------------------------------------------------------------------
// conv_hist: g_h0 = fp16(concat(ue, ie))  AND  g_cnt[r]++ per edge.
// Precondition: g_cnt == 0 (zero-init on load; re-zeroed by spmm epilogue).
// ---------------------------------------------------------------------------
__global__ void __launch_bounds__(256) conv_hist_kernel(const float4* __restrict__ ue,
                                                        const float4* __restrict__ ie,
                                                        const int* __restrict__ rows) {
    int i = blockIdx.x * blockDim.x + threadIdx.x;
    if (i < EE) atomicAdd(&g_cnt[__ldcs(&rows[i])], 1);
    if (i >= TOT8) return;
    float4 f0, f1;
    if (i < U8) {
        f0 = __ldg(&ue[2 * i]);        f1 = __ldg(&ue[2 * i + 1]);
    } else {
        f0 = __ldg(&ie[2 * (i - U8)]); f1 = __ldg(&ie[2 * (i - U8) + 1]);
    }
    uint4 h;
    h.x = h2u(__float22half2_rn(make_float2(f0.x, f0.y)));
    h.y = h2u(__float22half2_rn(make_float2(f0.z, f0.w)));
    h.z = h2u(__float22half2_rn(make_float2(f1.x, f1.y)));
    h.w = h2u(__float22half2_rn(make_float2(f1.z, f1.w)));
    reinterpret_cast<uint4*>(g_h0)[i] = h;
}

// ---------------------------------------------------------------------------
// Single-pass decoupled-lookback scan over g_cnt.
// Writes g_rowptr[r+1] (inclusive prefix) and g_cnt[r] = exclusive start
// (scatter cursor). Precondition: g_tile_state == 0.
// ---------------------------------------------------------------------------
__global__ void __launch_bounds__(256) scan_lookback_kernel() {
    __shared__ int s_warp[8];
    __shared__ int s_total;
    __shared__ uint32_t s_prefix;
    int tid = threadIdx.x;
    int blk = blockIdx.x;
    int base = blk * SCAN_TILE + tid * 16;

    int v[16];
    #pragma unroll
    for (int j = 0; j < 4; j++) {
        int idx = base + j * 4;
        if (idx + 3 < NN) {
            int4 t4 = *reinterpret_cast<const int4*>(&g_cnt[idx]);
            v[j*4] = t4.x; v[j*4+1] = t4.y; v[j*4+2] = t4.z; v[j*4+3] = t4.w;
        } else {
            v[j*4]   = (idx     < NN) ? g_cnt[idx]     : 0;
            v[j*4+1] = (idx + 1 < NN) ? g_cnt[idx + 1] : 0;
            v[j*4+2] = (idx + 2 < NN) ? g_cnt[idx + 2] : 0;
            v[j*4+3] = (idx + 3 < NN) ? g_cnt[idx + 3] : 0;
        }
    }
    int tsum = 0;
    #pragma unroll
    for (int j = 0; j < 16; j++) tsum += v[j];

    // block-wide inclusive scan of per-thread sums
    int lane = tid & 31, wid = tid >> 5;
    int x = tsum;
    #pragma unroll
    for (int d = 1; d < 32; d <<= 1) {
        int y = __shfl_up_sync(0xffffffffu, x, d);
        if (lane >= d) x += y;
    }
    if (lane == 31) s_warp[wid] = x;
    __syncthreads();
    if (wid == 0) {
        int w = (lane < 8) ? s_warp[lane] : 0;
        #pragma unroll
        for (int d = 1; d < 8; d <<= 1) {
            int y = __shfl_up_sync(0xffffffffu, w, d);
            if (lane >= d) w += y;
        }
        if (lane < 8) s_warp[lane] = w;
    }
    __syncthreads();
    int woff = (wid > 0) ? s_warp[wid - 1] : 0;
    int texcl = woff + x - tsum;          // this thread's exclusive prefix in block
    if (tid == 255) s_total = woff + x;   // block total
    __syncthreads();

    // warp 0: publish aggregate, windowed lookback, publish inclusive
    if (tid < 32) {
        if (blk == 0) {
            if (lane == 0) {
                s_prefix = 0;
                *(volatile unsigned long long*)&g_tile_state[0] =
                    (2ULL << 32) | (uint32_t)s_total;
            }
        } else {
            if (lane == 0)
                *(volatile unsigned long long*)&g_tile_state[blk] =
                    (1ULL << 32) | (uint32_t)s_total;
            unsigned long long prefix = 0;
            int b2 = blk - 1;
            while (true) {
                int p = b2 - lane;
                unsigned long long s;
                if (p < 0) {
                    s = (2ULL << 32);     // virtual predecessor: inclusive 0
                } else {
                    do { s = *(volatile unsigned long long*)&g_tile_state[p]; } while (s == 0ULL);
                }
                uint32_t st  = (uint32_t)(s >> 32);
                uint32_t val = (uint32_t)s;
                unsigned m = __ballot_sync(0xffffffffu, st == 2u);
                if (m) {
                    int k = __ffs(m) - 1;         // closest predecessor with inclusive
                    prefix += __reduce_add_sync(0xffffffffu, (lane <= k) ? val : 0u);
                    break;
                }
                prefix += __reduce_add_sync(0xffffffffu, val);
                b2 -= 32;
            }
            if (lane == 0) {
                s_prefix = (uint32_t)prefix;
                *(volatile unsigned long long*)&g_tile_state[blk] =
                    (2ULL << 32) | (uint32_t)(prefix + (uint32_t)s_total);
            }
        }
    }
    __syncthreads();

    int g = (int)s_prefix + texcl;        // global exclusive prefix at first item
    #pragma unroll
    for (int j = 0; j < 16; j++) {
        int idx = base + j;
        if (idx < NN) {
            g_cnt[idx] = g;               // scatter cursor (exclusive start)
            g_rowptr[idx + 1] = g + v[j]; // inclusive prefix
            g += v[j];
        }
    }
    if (blk == 0 && tid == 0) g_rowptr[0] = 0;
}

// ---------------------------------------------------------------------------
// scatter edges into row buckets
// ---------------------------------------------------------------------------
__global__ void __launch_bounds__(256) scatter_kernel(const int* __restrict__ rows,
                                                      const int* __restrict__ cols,
                                                      const float* __restrict__ vals) {
    int e = blockIdx.x * blockDim.x + threadIdx.x;
    if (e >= EE) return;
    int r = __ldcs(&rows[e]);
    int c = __ldcs(&cols[e]);
    float v = __ldcs(&vals[e]);
    int pos = atomicAdd(&g_cnt[r], 1);
    g_edges[pos] = make_int2(c, __float_as_int(v));
}

// ---------------------------------------------------------------------------
// CSR row accumulation core: simple loop, unroll 2 (ptxas batches the loads).
// 8 threads/row, fp32 accumulation.
// ---------------------------------------------------------------------------
__device__ __forceinline__ void csr_accum(int row, int ch,
                                          const __half* __restrict__ src,
                                          float2& a0, float2& a1,
                                          float2& a2, float2& a3) {
    int e   = __ldg(&g_rowptr[row]);
    int end = __ldg(&g_rowptr[row + 1]);
    a0 = make_float2(0.f, 0.f); a1 = a0; a2 = a0; a3 = a0;
    #pragma unroll 2
    for (; e < end; e++) {
        int2 ev = __ldg(&g_edges[e]);
        float v = __int_as_float(ev.y);
        uint4 x = __ldg(reinterpret_cast<const uint4*>(src + (size_t)ev.x * DD + ch));
        float2 f0 = __half22float2(u2h(x.x));
        float2 f1 = __half22float2(u2h(x.y));
        float2 f2 = __half22float2(u2h(x.z));
        float2 f3 = __half22float2(u2h(x.w));
        a0.x += v * f0.x; a0.y += v * f0.y;
        a1.x += v * f1.x; a1.y += v * f1.y;
        a2.x += v * f2.x; a2.y += v * f2.y;
        a3.x += v * f3.x; a3.y += v * f3.y;
    }
}

// layers 1 & 2: store fp16. Epilogue: restore invariants for next call
// (g_cnt = 0, tile state = 0) — cursors are dead once scatter has run.
__global__ void __launch_bounds__(256) csr_spmm_kernel(const __half* __restrict__ src,
                                                       __half* __restrict__ dst) {
    int t = blockIdx.x * blockDim.x + threadIdx.x;
    if (t < NN) g_cnt[t] = 0;
    if (t < NTILES) g_tile_state[t] = 0ULL;
    int row = t >> 3;
    if (row >= NN) return;
    int ch = (t & 7) << 3;
    float2 a0, a1, a2, a3;
    csr_accum(row, ch, src, a0, a1, a2, a3);
    uint4 o;
    o.x = h2u(__float22half2_rn(a0));
    o.y = h2u(__float22half2_rn(a1));
    o.z = h2u(__float22half2_rn(a2));
    o.w = h2u(__float22half2_rn(a3));
    *reinterpret_cast<uint4*>(dst + (size_t)row * DD + ch) = o;
}

// layer 3 fused with final: out = (ego + h1 + h2 + h3)*0.25, fp32
__global__ void __launch_bounds__(256) csr_spmm_final_kernel(
    const float4* __restrict__ ue, const float4* __restrict__ ie,
    float4* __restrict__ out) {
    int t = blockIdx.x * blockDim.x + threadIdx.x;
    int row = t >> 3;
    if (row >= NN) return;
    int ch = (t & 7) << 3;
    float2 a0, a1, a2, a3;
    csr_accum(row, ch, g_bufB, a0, a1, a2, a3);   // h3 accum from h2

    size_t base = (size_t)row * DD + ch;
    float4 e0, e1;
    if (row < NUM_USERS) {
        e0 = __ldg(&ue[base / 4]);       e1 = __ldg(&ue[base / 4 + 1]);
    } else {
        size_t ib = base - (size_t)NUM_USERS * DD;
        e0 = __ldg(&ie[ib / 4]);         e1 = __ldg(&ie[ib / 4 + 1]);
    }
    uint4 uh1 = __ldg(reinterpret_cast<const uint4*>(g_bufA + base));
    uint4 uh2 = __ldg(reinterpret_cast<const uint4*>(g_bufB + base));
    float2 h10 = __half22float2(u2h(uh1.x)), h11 = __half22float2(u2h(uh1.y));
    float2 h12 = __half22float2(u2h(uh1.z)), h13 = __half22float2(u2h(uh1.w));
    float2 h20 = __half22float2(u2h(uh2.x)), h21 = __half22float2(u2h(uh2.y));
    float2 h22 = __half22float2(u2h(uh2.z)), h23 = __half22float2(u2h(uh2.w));

    float4 o0, o1;
    o0.x = (e0.x + h10.x + h20.x + a0.x) * 0.25f;
    o0.y = (e0.y + h10.y + h20.y + a0.y) * 0.25f;
    o0.z = (e0.z + h11.x + h21.x + a1.x) * 0.25f;
    o0.w = (e0.w + h11.y + h21.y + a1.y) * 0.25f;
    o1.x = (e1.x + h12.x + h22.x + a2.x) * 0.25f;
    o1.y = (e1.y + h12.y + h22.y + a2.y) * 0.25f;
    o1.z = (e1.z + h13.x + h23.x + a3.x) * 0.25f;
    o1.w = (e1.w + h13.y + h23.y + a3.y) * 0.25f;
    out[base / 4]     = o0;
    out[base / 4 + 1] = o1;
}

extern "C" void kernel_launch(void* const* d_in, const int* in_sizes, int n_in,
                              void* d_out, int out_size) {
    const float* user_emb = (const float*)d_in[0];
    const float* item_emb = (const float*)d_in[1];
    const int*   adj_rows = (const int*)d_in[2];
    const int*   adj_cols = (const int*)d_in[3];
    const float* adj_vals = (const float*)d_in[4];
    float* out = (float*)d_out;

    __half *h0, *bufA, *bufB;
    cudaGetSymbolAddress((void**)&h0,   g_h0);
    cudaGetSymbolAddress((void**)&bufA, g_bufA);
    cudaGetSymbolAddress((void**)&bufB, g_bufB);

    const int T = 256;
    const int CONV_BLOCKS = (TOT8 + T - 1) / T;   // 9375 (covers EE/256=7813 too)
    const int EDGE_BLOCKS = (EE + T - 1) / T;
    const int SPMM_BLOCKS = (NN * 8 + T - 1) / T;

    // fp16 convert + row histogram (g_cnt==0 invariant holds on entry)
    conv_hist_kernel<<<CONV_BLOCKS, T>>>((const float4*)user_emb,
                                         (const float4*)item_emb, adj_rows);
    // one-pass scan: rowptr + scatter cursors
    scan_lookback_kernel<<<NTILES, T>>>();
    // edge scatter into row buckets
    scatter_kernel<<<EDGE_BLOCKS, T>>>(adj_rows, adj_cols, adj_vals);

    // h1 = A @ h0 ; h2 = A @ h1 ; out = (ego + h1 + h2 + A @ h2)/4
    csr_spmm_kernel<<<SPMM_BLOCKS, T>>>(h0,   bufA);
    csr_spmm_kernel<<<SPMM_BLOCKS, T>>>(bufA, bufB);
    csr_spmm_final_kernel<<<SPMM_BLOCKS, T>>>((const float4*)user_emb,
                                              (const float4*)item_emb, (float4*)out);
}